// round 5
// baseline (speedup 1.0000x reference)
#include <cuda_runtime.h>
#include <cstdint>
#include <cstddef>

// PoolingRetriever collapses: seqlen==1 -> softmax of single logit == 1.0
// -> out = (x@Wv.T + bv) @ Wo.T + bo.  Wq/bq/Wk/bk/q_state dead.
//
// R4 == R3 resubmit (R3 hit an infra flake, never ran):
// 8x8 register micro-tile (1 B/FMA, crossbar-balanced), conflict-free
// smem layouts (odd strides + column chunk permutation), FFMA2 throughout.

#define DIMX 768
#define NH   64
#define TM   128
#define NTHR 128
#define KC   32
#define XS_S 33   // xs row stride (odd -> conflict-free scalar col reads)
#define TMP_S 65  // tmp row stride

// Pre-transposed weights (scratch)
__device__ float g_WvT[DIMX * NH]; // [d][j] = Wv[j][d]
__device__ float g_WoT[NH * DIMX]; // [j][i] = Wo[i][j]

typedef unsigned long long u64t;

__device__ __forceinline__ u64t pack2(float lo, float hi) {
    u64t r; asm("mov.b64 %0, {%1, %2};" : "=l"(r) : "f"(lo), "f"(hi)); return r;
}
__device__ __forceinline__ void unpack2(u64t v, float& lo, float& hi) {
    asm("mov.b64 {%0, %1}, %2;" : "=f"(lo), "=f"(hi) : "l"(v));
}
__device__ __forceinline__ void fma2(u64t& d, u64t a, u64t b) {
    asm("fma.rn.f32x2 %0, %1, %2, %3;" : "=l"(d) : "l"(a), "l"(b), "l"(d));
}

__global__ void prep_kernel(const float* __restrict__ Wv,
                            const float* __restrict__ Wo) {
    int idx = blockIdx.x * blockDim.x + threadIdx.x;
    if (idx < DIMX * NH) {
        int d = idx / NH, j = idx % NH;
        g_WvT[idx] = Wv[j * DIMX + d];
    } else if (idx < 2 * DIMX * NH) {
        int t = idx - DIMX * NH;
        int j = t / DIMX, i = t % DIMX;
        g_WoT[t] = Wo[i * NH + j];
    }
}

// smem layout (bytes):
//  stage1: xs [TM][XS_S]   at 0        (128*33*4 = 16896)
//          ws [KC][64]     at 16896    (8192)            end 25088
//  stage2: tmp[TM][TMP_S]  at 0        (128*65*4 = 33280) (aliases stage1)
//          wo [32][64]     at 33280    (8192)            end 41472
#define SMEM_FLOATS (41472 / 4)
#define WS_OFF  (16896 / 4)
#define WO_OFF  (33280 / 4)

__global__ __launch_bounds__(NTHR) void fused_kernel(
        const float* __restrict__ x, const float* __restrict__ bv,
        const float* __restrict__ bo, float* __restrict__ out, int B) {
    __shared__ __align__(16) float smem[SMEM_FLOATS];
    float* xs  = smem;            // xs[r*XS_S + kk]
    float* ws  = smem + WS_OFF;   // ws[kk*64 + permuted col]
    float* tmp = smem;            // tmp[r*TMP_S + j]
    float* wo  = smem + WO_OFF;   // wo[j*64 + permuted col]

    const int tid = threadIdx.x;
    const int tx = tid & 7;        // 8 col-groups -> cols tx*8..tx*8+7
    const int ty = tid >> 3;       // 16 row-groups -> rows ty*8..ty*8+7
    const int brow = blockIdx.x * TM;

    // loader lanes
    const int la = tid & 7,  lr = tid >> 3;   // x tile: kk-quad, row
    const int wc = tid & 15, wk = tid >> 4;   // weight tile: col-quad, row

    // ----- Stage 1: tmp[128][64] = x @ Wv.T + bv -----
    u64t acc[8][4];
    {
        float4 b0 = *(const float4*)&bv[tx * 8];
        float4 b1 = *(const float4*)&bv[tx * 8 + 4];
        u64t p0 = pack2(b0.x, b0.y), p1 = pack2(b0.z, b0.w);
        u64t p2 = pack2(b1.x, b1.y), p3 = pack2(b1.z, b1.w);
        #pragma unroll
        for (int i = 0; i < 8; i++) {
            acc[i][0] = p0; acc[i][1] = p1; acc[i][2] = p2; acc[i][3] = p3;
        }
    }

    for (int k0 = 0; k0 < DIMX; k0 += KC) {
        // fill xs: conflict-free scalar stores (stride 33)
        #pragma unroll
        for (int p = 0; p < 8; p++) {
            int r = lr + p * 16;
            int gr = brow + r; if (gr >= B) gr = B - 1;
            float4 v = *(const float4*)&x[(size_t)gr * DIMX + k0 + la * 4];
            float* d = &xs[r * XS_S + la * 4];
            d[0] = v.x; d[1] = v.y; d[2] = v.z; d[3] = v.w;
        }
        // fill ws with column-chunk permutation
        #pragma unroll
        for (int p = 0; p < 4; p++) {
            int kk = wk + p * 8;
            float4 v = *(const float4*)&g_WvT[(k0 + kk) * NH + wc * 4];
            int pc = ((wc & 1) * 8 + (wc >> 1)) * 4;
            *(float4*)&ws[kk * 64 + pc] = v;
        }
        __syncthreads();

        #pragma unroll 4
        for (int kk = 0; kk < KC; kk++) {
            float4 bl = *(const float4*)&ws[kk * 64 + tx * 4];       // cols 8tx..+3
            float4 bh = *(const float4*)&ws[kk * 64 + 32 + tx * 4];  // cols 8tx+4..+7
            u64t b01 = pack2(bl.x, bl.y), b23 = pack2(bl.z, bl.w);
            u64t b45 = pack2(bh.x, bh.y), b67 = pack2(bh.z, bh.w);
            #pragma unroll
            for (int i = 0; i < 8; i++) {
                float a = xs[(ty * 8 + i) * XS_S + kk];
                u64t aa = pack2(a, a);
                fma2(acc[i][0], aa, b01); fma2(acc[i][1], aa, b23);
                fma2(acc[i][2], aa, b45); fma2(acc[i][3], aa, b67);
            }
        }
        __syncthreads();
    }

    // write tmp (stage-1 smem now dead; tmp aliases it)
    #pragma unroll
    for (int i = 0; i < 8; i++) {
        float* d = &tmp[(ty * 8 + i) * TMP_S + tx * 8];
        float v0, v1;
        #pragma unroll
        for (int p = 0; p < 4; p++) {
            unpack2(acc[i][p], v0, v1);
            d[2 * p] = v0; d[2 * p + 1] = v1;
        }
    }
    __syncthreads();

    // ----- Stage 2: out[128][768] = tmp @ Wo.T + bo -----
    for (int i0 = 0; i0 < DIMX; i0 += 64) {
        u64t acc2[8][4];
        {
            float4 b0 = *(const float4*)&bo[i0 + tx * 8];
            float4 b1 = *(const float4*)&bo[i0 + tx * 8 + 4];
            u64t p0 = pack2(b0.x, b0.y), p1 = pack2(b0.z, b0.w);
            u64t p2 = pack2(b1.x, b1.y), p3 = pack2(b1.z, b1.w);
            #pragma unroll
            for (int i = 0; i < 8; i++) {
                acc2[i][0] = p0; acc2[i][1] = p1; acc2[i][2] = p2; acc2[i][3] = p3;
            }
        }

        #pragma unroll
        for (int jh = 0; jh < NH; jh += 32) {
            // fill wo rows jh..jh+31 (permuted cols)
            #pragma unroll
            for (int p = 0; p < 4; p++) {
                int j = wk + p * 8;
                float4 v = *(const float4*)&g_WoT[(jh + j) * DIMX + i0 + wc * 4];
                int pc = ((wc & 1) * 8 + (wc >> 1)) * 4;
                *(float4*)&wo[j * 64 + pc] = v;
            }
            __syncthreads();

            #pragma unroll 4
            for (int kk = 0; kk < 32; kk++) {
                float4 bl = *(const float4*)&wo[kk * 64 + tx * 4];
                float4 bh = *(const float4*)&wo[kk * 64 + 32 + tx * 4];
                u64t b01 = pack2(bl.x, bl.y), b23 = pack2(bl.z, bl.w);
                u64t b45 = pack2(bh.x, bh.y), b67 = pack2(bh.z, bh.w);
                #pragma unroll
                for (int i = 0; i < 8; i++) {
                    float a = tmp[(ty * 8 + i) * TMP_S + jh + kk];
                    u64t aa = pack2(a, a);
                    fma2(acc2[i][0], aa, b01); fma2(acc2[i][1], aa, b23);
                    fma2(acc2[i][2], aa, b45); fma2(acc2[i][3], aa, b67);
                }
            }
            __syncthreads();
        }

        // store out tile
        #pragma unroll
        for (int i = 0; i < 8; i++) {
            int gr = brow + ty * 8 + i;
            if (gr < B) {
                float4 o0, o1;
                unpack2(acc2[i][0], o0.x, o0.y);
                unpack2(acc2[i][1], o0.z, o0.w);
                unpack2(acc2[i][2], o1.x, o1.y);
                unpack2(acc2[i][3], o1.z, o1.w);
                float* d = &out[(size_t)gr * DIMX + i0 + tx * 8];
                *(float4*)&d[0] = o0;
                *(float4*)&d[4] = o1;
            }
        }
    }
}

extern "C" void kernel_launch(void* const* d_in, const int* in_sizes, int n_in,
                              void* d_out, int out_size) {
    // metadata order: x, q_state, Wq, bq, Wk, bk, Wv, bv, Wo, bo
    const float* x  = (const float*)d_in[0];
    const float* Wv = (const float*)d_in[6];
    const float* bv = (const float*)d_in[7];
    const float* Wo = (const float*)d_in[8];
    const float* bo = (const float*)d_in[9];
    float* out = (float*)d_out;

    const int B = in_sizes[0] / DIMX;

    prep_kernel<<<(2 * DIMX * NH + 255) / 256, 256>>>(Wv, Wo);
    const int grid = (B + TM - 1) / TM;
    fused_kernel<<<grid, NTHR>>>(x, bv, bo, out, B);
}

// round 9
// speedup vs baseline: 2.1802x; 2.1802x over previous
#include <cuda_runtime.h>
#include <cuda_bf16.h>
#include <cstdint>
#include <cstddef>

// PoolingRetriever collapses: seqlen==1 -> softmax of one logit == 1
// -> out = (x@Wv.T + bv) @ Wo.T + bo.   Wq/bq/Wk/bk/q_state dead.
// R6: mma.sync.m16n8k16 bf16, 3-pass hi/lo split (tcgen05 is sm_103a-gated;
// harness compiles compute_103, so legacy HMMA is the tensor path).

#define DIMX 768
#define NH   64
#define TM   128
#define NTHR 256
#define KC   64                 // x K-chunk (bf16 row = 128 B = SW128 atom)
#define NCHUNK (DIMX / KC)      // 12

// smem (dynamic, bytes)
#define OFF_XH 0
#define OFF_XL 16384
#define OFF_TH 32768
#define OFF_TL 49152
#define SMEM_TOTAL 65536

// B fragments prepped in gmem, per-lane mma layout.
// Wv: [ktg 0..47][nt 0..7][lane 0..31] -> uint2 {b0,b1}
// Wo: [nt 0..95][kt 0..3][lane 0..31] -> uint2 {b0,b1}
__device__ __align__(16) uint2 g_wv_fh[48 * 8 * 32];
__device__ __align__(16) uint2 g_wv_fl[48 * 8 * 32];
__device__ __align__(16) uint2 g_wo_fh[96 * 4 * 32];
__device__ __align__(16) uint2 g_wo_fl[96 * 4 * 32];

static __device__ __forceinline__ uint32_t smem_u32(const void* p) {
    uint32_t a;
    asm("{ .reg .u64 t; cvta.to.shared.u64 t, %1; cvt.u32.u64 %0, t; }"
        : "=r"(a) : "l"(p));
    return a;
}
static __device__ __forceinline__ uint32_t swz(uint32_t b) {
    return b ^ ((b >> 3) & 0x70);
}
static __device__ __forceinline__ void split1(float v, __nv_bfloat16& h,
                                              __nv_bfloat16& l) {
    h = __float2bfloat16(v);
    l = __float2bfloat16(v - __bfloat162float(h));
}
static __device__ __forceinline__ uint32_t packbf(__nv_bfloat16 lo,
                                                  __nv_bfloat16 hi) {
    __nv_bfloat162 t; t.x = lo; t.y = hi;
    return *(uint32_t*)&t;
}

#define LDMX4(r0, r1, r2, r3, addr)                                          \
    asm volatile("ldmatrix.sync.aligned.m8n8.x4.shared.b16 {%0,%1,%2,%3}, [%4];" \
                 : "=r"(r0), "=r"(r1), "=r"(r2), "=r"(r3) : "r"(addr))

static __device__ __forceinline__ void mma16816(float* c, const uint32_t* a,
                                                uint2 b) {
    asm volatile(
        "mma.sync.aligned.m16n8k16.row.col.f32.bf16.bf16.f32 "
        "{%0,%1,%2,%3}, {%4,%5,%6,%7}, {%8,%9}, {%0,%1,%2,%3};"
        : "+f"(c[0]), "+f"(c[1]), "+f"(c[2]), "+f"(c[3])
        : "r"(a[0]), "r"(a[1]), "r"(a[2]), "r"(a[3]), "r"(b.x), "r"(b.y));
}

// ---------------- prep: split weights into per-lane B fragments -------------
__global__ void prep_kernel(const float* __restrict__ Wv,
                            const float* __restrict__ Wo) {
    int idx = blockIdx.x * blockDim.x + threadIdx.x;
    if (idx < 48 * 8 * 32) {
        int lane = idx & 31, nt = (idx >> 5) & 7, ktg = idx >> 8;
        int n = nt * 8 + (lane >> 2);
        int k = ktg * 16 + (lane & 3) * 2;
        float w0 = Wv[n * DIMX + k],     w1 = Wv[n * DIMX + k + 1];
        float w2 = Wv[n * DIMX + k + 8], w3 = Wv[n * DIMX + k + 9];
        __nv_bfloat16 h0, l0, h1, l1, h2, l2, h3, l3;
        split1(w0, h0, l0); split1(w1, h1, l1);
        split1(w2, h2, l2); split1(w3, h3, l3);
        g_wv_fh[idx] = make_uint2(packbf(h0, h1), packbf(h2, h3));
        g_wv_fl[idx] = make_uint2(packbf(l0, l1), packbf(l2, l3));
    } else if (idx < 2 * 12288) {
        int t = idx - 12288;
        int lane = t & 31, kt = (t >> 5) & 3, nt = t >> 7;
        int n = nt * 8 + (lane >> 2);        // out column 0..767
        int k = kt * 16 + (lane & 3) * 2;    // 0..63
        float w0 = Wo[n * NH + k],     w1 = Wo[n * NH + k + 1];
        float w2 = Wo[n * NH + k + 8], w3 = Wo[n * NH + k + 9];
        __nv_bfloat16 h0, l0, h1, l1, h2, l2, h3, l3;
        split1(w0, h0, l0); split1(w1, h1, l1);
        split1(w2, h2, l2); split1(w3, h3, l3);
        g_wo_fh[t] = make_uint2(packbf(h0, h1), packbf(h2, h3));
        g_wo_fl[t] = make_uint2(packbf(l0, l1), packbf(l2, l3));
    }
}

// ---------------- fused HMMA kernel -----------------------------------------
__global__ __launch_bounds__(NTHR, 2) void fused_kernel(
        const float* __restrict__ x, const float* __restrict__ bv,
        const float* __restrict__ bo, float* __restrict__ out, int B) {
    extern __shared__ __align__(128) char smem[];
    const uint32_t sb = smem_u32(smem);
    const int tid = threadIdx.x;
    const int wid = tid >> 5, lane = tid & 31;
    const int wm = wid >> 1, wn = wid & 1;   // warps: 4 (M) x 2 (N)
    const int brow = blockIdx.x * TM;
    const int lrow = lane >> 2, lk2 = (lane & 3) * 2;

    // ----- Stage 1: tmp[128x64] = x @ Wv.T (3-pass), accum in regs -----
    float c1[2][4][4];
    #pragma unroll
    for (int mt = 0; mt < 2; mt++)
        #pragma unroll
        for (int nt = 0; nt < 4; nt++)
            #pragma unroll
            for (int q = 0; q < 4; q++) c1[mt][nt][q] = 0.0f;

    for (int ch = 0; ch < NCHUNK; ch++) {
        // load + split x chunk [128 x 64] into swizzled smem
        #pragma unroll
        for (int s = 0; s < 8; s++) {
            int f4 = s * NTHR + tid;
            int r = f4 >> 4, k4 = f4 & 15;
            int gr = brow + r; if (gr >= B) gr = B - 1;
            float4 v = *(const float4*)&x[(size_t)gr * DIMX + ch * KC + k4 * 4];
            __nv_bfloat16 h0, l0, h1, l1, h2, l2, h3, l3;
            split1(v.x, h0, l0); split1(v.y, h1, l1);
            split1(v.z, h2, l2); split1(v.w, h3, l3);
            uint32_t so = swz((uint32_t)(r * 128 + k4 * 8));
            *(uint2*)(smem + OFF_XH + so) =
                make_uint2(packbf(h0, h1), packbf(h2, h3));
            *(uint2*)(smem + OFF_XL + so) =
                make_uint2(packbf(l0, l1), packbf(l2, l3));
        }
        __syncthreads();

        #pragma unroll
        for (int kt = 0; kt < 4; kt++) {
            int ktg = ch * 4 + kt;
            uint32_t ah[2][4], al[2][4];
            #pragma unroll
            for (int mt = 0; mt < 2; mt++) {
                uint32_t lb = (uint32_t)((wm * 32 + mt * 16 + (lane & 15)) * 128 +
                                         kt * 32 + (lane >> 4) * 16);
                uint32_t so = swz(lb);
                LDMX4(ah[mt][0], ah[mt][1], ah[mt][2], ah[mt][3],
                      sb + OFF_XH + so);
                LDMX4(al[mt][0], al[mt][1], al[mt][2], al[mt][3],
                      sb + OFF_XL + so);
            }
            #pragma unroll
            for (int nt = 0; nt < 4; nt++) {
                int ntg = wn * 4 + nt;
                uint2 bh = g_wv_fh[(ktg * 8 + ntg) * 32 + lane];
                uint2 bl = g_wv_fl[(ktg * 8 + ntg) * 32 + lane];
                #pragma unroll
                for (int mt = 0; mt < 2; mt++) {
                    mma16816(c1[mt][nt], ah[mt], bh);
                    mma16816(c1[mt][nt], ah[mt], bl);
                    mma16816(c1[mt][nt], al[mt], bh);
                }
            }
        }
        __syncthreads();
    }

    // ----- stage-1 epilogue: +bv, split, store tmp hi/lo swizzled -----
    #pragma unroll
    for (int mt = 0; mt < 2; mt++) {
        #pragma unroll
        for (int nt = 0; nt < 4; nt++) {
            int c = wn * 32 + nt * 8 + lk2;
            float b0 = __ldg(&bv[c]), b1 = __ldg(&bv[c + 1]);
            int r0 = wm * 32 + mt * 16 + lrow;
            float v0 = c1[mt][nt][0] + b0, v1 = c1[mt][nt][1] + b1;
            float v2 = c1[mt][nt][2] + b0, v3 = c1[mt][nt][3] + b1;
            __nv_bfloat16 h0, l0, h1, l1, h2, l2, h3, l3;
            split1(v0, h0, l0); split1(v1, h1, l1);
            split1(v2, h2, l2); split1(v3, h3, l3);
            uint32_t s0 = swz((uint32_t)(r0 * 128 + c * 2));
            uint32_t s1 = swz((uint32_t)((r0 + 8) * 128 + c * 2));
            *(uint32_t*)(smem + OFF_TH + s0) = packbf(h0, h1);
            *(uint32_t*)(smem + OFF_TL + s0) = packbf(l0, l1);
            *(uint32_t*)(smem + OFF_TH + s1) = packbf(h2, h3);
            *(uint32_t*)(smem + OFF_TL + s1) = packbf(l2, l3);
        }
    }
    __syncthreads();

    // ----- Stage 2: out[128x768] = tmp @ Wo.T + bo -----
    uint32_t a2h[2][4][4], a2l[2][4][4];
    #pragma unroll
    for (int mt = 0; mt < 2; mt++) {
        #pragma unroll
        for (int kt = 0; kt < 4; kt++) {
            uint32_t lb = (uint32_t)((wm * 32 + mt * 16 + (lane & 15)) * 128 +
                                     kt * 32 + (lane >> 4) * 16);
            uint32_t so = swz(lb);
            LDMX4(a2h[mt][kt][0], a2h[mt][kt][1], a2h[mt][kt][2],
                  a2h[mt][kt][3], sb + OFF_TH + so);
            LDMX4(a2l[mt][kt][0], a2l[mt][kt][1], a2l[mt][kt][2],
                  a2l[mt][kt][3], sb + OFF_TL + so);
        }
    }

    for (int ct = 0; ct < 48; ct++) {
        int ntg = wn * 48 + ct;
        uint2 bh[4], bl[4];
        #pragma unroll
        for (int kt = 0; kt < 4; kt++) {
            bh[kt] = g_wo_fh[(ntg * 4 + kt) * 32 + lane];
            bl[kt] = g_wo_fl[(ntg * 4 + kt) * 32 + lane];
        }
        float cc[2][4];
        #pragma unroll
        for (int mt = 0; mt < 2; mt++)
            #pragma unroll
            for (int q = 0; q < 4; q++) cc[mt][q] = 0.0f;
        #pragma unroll
        for (int mt = 0; mt < 2; mt++) {
            #pragma unroll
            for (int kt = 0; kt < 4; kt++) {
                mma16816(cc[mt], a2h[mt][kt], bh[kt]);
                mma16816(cc[mt], a2h[mt][kt], bl[kt]);
                mma16816(cc[mt], a2l[mt][kt], bh[kt]);
            }
        }
        int c = ntg * 8 + lk2;
        float2 bb = *(const float2*)&bo[c];
        #pragma unroll
        for (int mt = 0; mt < 2; mt++) {
            int gr = brow + wm * 32 + mt * 16 + lrow;
            if (gr < B) {
                float2 o0 = make_float2(cc[mt][0] + bb.x, cc[mt][1] + bb.y);
                float2 o1 = make_float2(cc[mt][2] + bb.x, cc[mt][3] + bb.y);
                *(float2*)&out[(size_t)gr * DIMX + c] = o0;
                if (gr + 8 < B)
                    *(float2*)&out[(size_t)(gr + 8) * DIMX + c] = o1;
            }
        }
    }
}

extern "C" void kernel_launch(void* const* d_in, const int* in_sizes, int n_in,
                              void* d_out, int out_size) {
    // metadata order: x, q_state, Wq, bq, Wk, bk, Wv, bv, Wo, bo
    const float* x  = (const float*)d_in[0];
    const float* Wv = (const float*)d_in[6];
    const float* bv = (const float*)d_in[7];
    const float* Wo = (const float*)d_in[8];
    const float* bo = (const float*)d_in[9];
    float* out = (float*)d_out;

    const int B = in_sizes[0] / DIMX;

    cudaFuncSetAttribute(fused_kernel,
                         cudaFuncAttributeMaxDynamicSharedMemorySize,
                         SMEM_TOTAL);

    prep_kernel<<<(2 * 12288 + 255) / 256, 256>>>(Wv, Wo);
    const int grid = (B + TM - 1) / TM;
    fused_kernel<<<grid, NTHR, SMEM_TOTAL>>>(x, bv, bo, out, B);
}